// round 12
// baseline (speedup 1.0000x reference)
#include <cuda_runtime.h>
#include <cuda_bf16.h>
#include <cstdint>

// ============================================================================
// TernaryLinear: out[8192,4096] = x[8192,4096] @ W[4096,4096]^T + bias
//
// R9 = R4 skeleton (256 thr, 8 warps, coarse hi/lo phase stagger, ~150 regs)
// with the R7/R8-validated balanced split:
//   tensor: hi pass ks 0..2  -> 48 mma/SMSP/iter = 3072 cyc floor
//   dp4a:   lo pass kc 0..7 + hi pass kc 6..7 -> 2560 slots/SMSP/iter
// plus single top-of-iter __syncthreads (prefetch distance 2, NSTAGE 4).
// out = s*(256*(hi_mma+hi_dp) + lo) + bias, all-int accumulation (exact).
// ============================================================================

#define M_DIM 8192
#define N_DIM 4096
#define K_DIM 4096
#define BM 64
#define BN 128
#define BK 128                     // int8 elems per K tile (128 B/row)
#define NKT (K_DIM / BK)           // 32
#define NSTAGE 4
#define A_HI_OFF 0
#define A_LO_OFF 8192
#define B_OFF    16384
#define STAGE_BYTES 32768          // A_hi 8K + A_lo 8K + B 16K
#define SMEM_TOTAL (NSTAGE * STAGE_BYTES)   // 128 KB

// Static device scratch (sanctioned workaround for no-alloc rule)
__device__ __align__(128) int8_t g_xh8[(size_t)M_DIM * K_DIM];
__device__ __align__(128) int8_t g_xl8[(size_t)M_DIM * K_DIM];
__device__ __align__(128) int8_t g_w8 [(size_t)N_DIM * K_DIM];
__device__ __align__(128) float  g_scale[M_DIM];

// ---------------------------------------------------------------------------
// PTX helpers
// ---------------------------------------------------------------------------
__device__ __forceinline__ uint32_t smem_u32(const void* p) {
    uint32_t a;
    asm("{ .reg .u64 t; cvta.to.shared.u64 t, %1; cvt.u32.u64 %0, t; }"
        : "=r"(a) : "l"(p));
    return a;
}

#define CP16(dst, src) \
    asm volatile("cp.async.cg.shared.global [%0], [%1], 16;" \
                 :: "r"((uint32_t)(dst)), "l"(src) : "memory")
#define CP_COMMIT() asm volatile("cp.async.commit_group;" ::: "memory")
#define CP_WAIT1()  asm volatile("cp.async.wait_group 1;" ::: "memory")

#define LDSM4(r0, r1, r2, r3, addr) \
    asm volatile("ldmatrix.sync.aligned.m8n8.x4.shared.b16 {%0,%1,%2,%3}, [%4];" \
                 : "=r"(r0), "=r"(r1), "=r"(r2), "=r"(r3) : "r"(addr))

__device__ __forceinline__ void mma_s8(int c[4], const uint32_t a[4],
                                       uint32_t b0, uint32_t b1) {
    asm volatile(
        "mma.sync.aligned.m16n8k32.row.col.s32.s8.s8.s32 "
        "{%0,%1,%2,%3}, {%4,%5,%6,%7}, {%8,%9}, {%0,%1,%2,%3};"
        : "+r"(c[0]), "+r"(c[1]), "+r"(c[2]), "+r"(c[3])
        : "r"(a[0]), "r"(a[1]), "r"(a[2]), "r"(a[3]), "r"(b0), "r"(b1));
}

// ---------------------------------------------------------------------------
// Merged pre-pass: blocks [0,8192) quantize x rows; [8192, 24576) convert W.
// ---------------------------------------------------------------------------
__global__ void __launch_bounds__(256) quant_all_kernel(const float* __restrict__ x,
                                                        const float* __restrict__ w) {
    const int t = threadIdx.x;
    if (blockIdx.x < M_DIM) {
        const int row = blockIdx.x;
        const float4* xr = reinterpret_cast<const float4*>(x + (size_t)row * K_DIM);
        float4 v[4];
        float amax = 0.f;
#pragma unroll
        for (int p = 0; p < 4; ++p) {
            v[p] = xr[p * 256 + t];
            amax = fmaxf(amax, fmaxf(fmaxf(fabsf(v[p].x), fabsf(v[p].y)),
                                     fmaxf(fabsf(v[p].z), fabsf(v[p].w))));
        }
#pragma unroll
        for (int o = 16; o; o >>= 1)
            amax = fmaxf(amax, __shfl_xor_sync(0xFFFFFFFFu, amax, o));

        __shared__ float smax[8];
        if ((t & 31) == 0) smax[t >> 5] = amax;
        __syncthreads();
        float bmax = fmaxf(fmaxf(fmaxf(smax[0], smax[1]), fmaxf(smax[2], smax[3])),
                           fmaxf(fmaxf(smax[4], smax[5]), fmaxf(smax[6], smax[7])));

        const float inv = (bmax > 0.f) ? (32639.f / bmax) : 0.f;
        if (t == 0) g_scale[row] = (bmax > 0.f) ? (bmax / 32639.f) : 0.f;

        char4* hp = reinterpret_cast<char4*>(g_xh8 + (size_t)row * K_DIM);
        char4* lp = reinterpret_cast<char4*>(g_xl8 + (size_t)row * K_DIM);
#pragma unroll
        for (int p = 0; p < 4; ++p) {
            int q0 = __float2int_rn(v[p].x * inv);
            int q1 = __float2int_rn(v[p].y * inv);
            int q2 = __float2int_rn(v[p].z * inv);
            int q3 = __float2int_rn(v[p].w * inv);
            int h0 = (q0 + 128) >> 8, h1 = (q1 + 128) >> 8;
            int h2 = (q2 + 128) >> 8, h3 = (q3 + 128) >> 8;
            char4 hc = make_char4((char)h0, (char)h1, (char)h2, (char)h3);
            char4 lc = make_char4((char)(q0 - (h0 << 8)), (char)(q1 - (h1 << 8)),
                                  (char)(q2 - (h2 << 8)), (char)(q3 - (h3 << 8)));
            hp[p * 256 + t] = hc;
            lp[p * 256 + t] = lc;
        }
    } else {
        size_t i = (size_t)(blockIdx.x - M_DIM) * 256 + t;   // float4 index
        float4 v = reinterpret_cast<const float4*>(w)[i];
        char4 c = make_char4((char)__float2int_rn(v.x), (char)__float2int_rn(v.y),
                             (char)__float2int_rn(v.z), (char)__float2int_rn(v.w));
        reinterpret_cast<char4*>(g_w8)[i] = c;
    }
}

// ---------------------------------------------------------------------------
// Main hybrid GEMM. CTA 64x128, 256 thr = 8 warps (2m x 4n hi-tiles 32x32).
//   mma part (ks 0..2): accH[2][4][4], 24 mma/warp/iter.
//   dp4a part: accLo[8][4] (lo kc 0..7) + accHd[8][4] (hi kc 6..7);
//              rows wid+8i (broadcast A loads), cols lane+32j.
// Coarse stagger: warps 0-3 mma->dp4a, warps 4-7 dp4a->mma (SMSP pairs).
// 4-stage cp.async ring, prefetch distance 2, one __syncthreads per iter.
// ---------------------------------------------------------------------------
__global__ void __launch_bounds__(256, 1)
gemm_s8_kernel(const float* __restrict__ bias, float* __restrict__ out) {
    extern __shared__ char smem[];
    const uint32_t sb = smem_u32(smem);
    const int tid = threadIdx.x;
    const int lane = tid & 31;
    const int wid = tid >> 5;
    const int wm = wid >> 2;           // 0..1
    const int wn = wid & 3;            // 0..3
    const int m0 = blockIdx.y * BM;
    const int n0 = blockIdx.x * BN;

    // --- cp.async mapping (8 x 16B chunks per thread = 32 KB/stage) ---
    const int arow = tid >> 2;
    const int acol = (tid & 3) * 2;
    const int8_t* gH = g_xh8 + (size_t)(m0 + arow) * K_DIM + acol * 16;
    const int8_t* gL = g_xl8 + (size_t)(m0 + arow) * K_DIM + acol * 16;
    const uint32_t aBase = (uint32_t)arow * BK;
    const uint32_t asw0 = aBase + (uint32_t)(((acol + 0) ^ (arow & 7)) << 4);
    const uint32_t asw1 = aBase + (uint32_t)(((acol + 1) ^ (arow & 7)) << 4);
    const int brow = tid >> 1;
    const int bcol = (tid & 1) * 4;
    const int8_t* gW = g_w8 + (size_t)(n0 + brow) * K_DIM + bcol * 16;
    const uint32_t bBase = B_OFF + (uint32_t)brow * BK;
    uint32_t bsw[4];
#pragma unroll
    for (int j = 0; j < 4; ++j)
        bsw[j] = bBase + (uint32_t)(((bcol + j) ^ (brow & 7)) << 4);

#define PREFETCH(it) do {                                                     \
    const int _k = (it) * BK;                                                 \
    const uint32_t _s = sb + (uint32_t)((it) & (NSTAGE - 1)) * STAGE_BYTES;   \
    CP16(_s + A_HI_OFF + asw0, gH + _k);                                      \
    CP16(_s + A_HI_OFF + asw1, gH + _k + 16);                                 \
    CP16(_s + A_LO_OFF + asw0, gL + _k);                                      \
    CP16(_s + A_LO_OFF + asw1, gL + _k + 16);                                 \
    CP16(_s + bsw[0], gW + _k);                                               \
    CP16(_s + bsw[1], gW + _k + 16);                                          \
    CP16(_s + bsw[2], gW + _k + 32);                                          \
    CP16(_s + bsw[3], gW + _k + 48);                                          \
} while (0)

    // --- hi-path ldmatrix lane addressing ---
    const int ag = lane >> 3;
    const int aRow0 = wm * 32 + ((ag & 1) << 3) + (lane & 7);
    const int agc = ag >> 1;
    const int bRow = wn * 32 + lane;
    const uint32_t bRowOff = B_OFF + (uint32_t)bRow * BK;
    const int bRowSw = bRow & 7;

    int accH[2][4][4];
#pragma unroll
    for (int mt = 0; mt < 2; ++mt)
#pragma unroll
        for (int nt = 0; nt < 4; ++nt)
#pragma unroll
            for (int i = 0; i < 4; ++i) accH[mt][nt][i] = 0;

    // --- dp4a-path setup: rows wid+8i (warp-uniform A), cols lane+32j ---
    int accLo[8][4], accHd[8][4];
#pragma unroll
    for (int i = 0; i < 8; ++i)
#pragma unroll
        for (int j = 0; j < 4; ++j) { accLo[i][j] = 0; accHd[i][j] = 0; }
    const uint32_t loASw = (uint32_t)(wid & 7);             // warp-uniform
    uint32_t loBOff[4];
#pragma unroll
    for (int j = 0; j < 4; ++j)
        loBOff[j] = B_OFF + (uint32_t)(lane + 32 * j) * BK;
    const uint32_t loBSw = (uint32_t)(lane & 7);

    // --- prologue: fill 2 stages (prefetch distance 2) ---
    PREFETCH(0); CP_COMMIT();
    PREFETCH(1); CP_COMMIT();

    for (int it = 0; it < NKT; ++it) {
        CP_WAIT1();            // stage `it` resident (1 group still in flight)
        __syncthreads();       // visibility + WAR for stage (it+2)&3
        if (it + 2 < NKT) { PREFETCH(it + 2); }
        CP_COMMIT();

        const uint32_t So = (uint32_t)(it & (NSTAGE - 1)) * STAGE_BYTES;
        const uint32_t S = sb + So;

        auto mma_part = [&]() {
#pragma unroll
            for (int ks = 0; ks < 3; ++ks) {
                uint32_t b0[4], b1[4];
                {
                    uint32_t a0 = S + bRowOff + (uint32_t)(((ks * 2)     ^ bRowSw) << 4);
                    uint32_t a1 = S + bRowOff + (uint32_t)(((ks * 2 + 1) ^ bRowSw) << 4);
                    LDSM4(b0[0], b0[1], b0[2], b0[3], a0);
                    LDSM4(b1[0], b1[1], b1[2], b1[3], a1);
                }
                uint32_t ah[2][4];
#pragma unroll
                for (int mt = 0; mt < 2; ++mt) {
                    const int rA = aRow0 + mt * 16;
                    const int cA = ks * 2 + agc;
                    const uint32_t off = (uint32_t)rA * BK +
                                         (uint32_t)((cA ^ (rA & 7)) << 4);
                    LDSM4(ah[mt][0], ah[mt][1], ah[mt][2], ah[mt][3],
                          S + A_HI_OFF + off);
                }
#pragma unroll
                for (int mt = 0; mt < 2; ++mt)
#pragma unroll
                    for (int nt = 0; nt < 4; ++nt)
                        mma_s8(accH[mt][nt], ah[mt], b0[nt], b1[nt]);
            }
        };

        auto dp_part = [&]() {
#pragma unroll 1
            for (int kc = 0; kc < 8; ++kc) {
                uint4 bw[4];
#pragma unroll
                for (int j = 0; j < 4; ++j)
                    bw[j] = *reinterpret_cast<const uint4*>(
                        smem + So + loBOff[j] + (((uint32_t)kc ^ loBSw) << 4));
#pragma unroll
                for (int i = 0; i < 8; ++i) {
                    const uint4 aw = *reinterpret_cast<const uint4*>(
                        smem + So + A_LO_OFF +
                        (uint32_t)(wid + 8 * i) * BK + (((uint32_t)kc ^ loASw) << 4));
#pragma unroll
                    for (int j = 0; j < 4; ++j) {
                        int a = accLo[i][j];
                        a = __dp4a((int)aw.x, (int)bw[j].x, a);
                        a = __dp4a((int)aw.y, (int)bw[j].y, a);
                        a = __dp4a((int)aw.z, (int)bw[j].z, a);
                        a = __dp4a((int)aw.w, (int)bw[j].w, a);
                        accLo[i][j] = a;
                    }
                }
                if (kc >= 6) {   // hi pass ks=3 on dp4a (reuses bw)
#pragma unroll
                    for (int i = 0; i < 8; ++i) {
                        const uint4 aw = *reinterpret_cast<const uint4*>(
                            smem + So + A_HI_OFF +
                            (uint32_t)(wid + 8 * i) * BK + (((uint32_t)kc ^ loASw) << 4));
#pragma unroll
                        for (int j = 0; j < 4; ++j) {
                            int a = accHd[i][j];
                            a = __dp4a((int)aw.x, (int)bw[j].x, a);
                            a = __dp4a((int)aw.y, (int)bw[j].y, a);
                            a = __dp4a((int)aw.z, (int)bw[j].z, a);
                            a = __dp4a((int)aw.w, (int)bw[j].w, a);
                            accHd[i][j] = a;
                        }
                    }
                }
            }
        };

        // Coarse phase stagger: SMSP s hosts warps s (hi-first) and s+4
        // (lo-first) -> tensor and fma pipes fed concurrently.
        if (wid < 4) { mma_part(); dp_part(); }
        else         { dp_part(); mma_part(); }
    }

    // --- stage dp4a accumulators: lo at [0,32K), hiK3 at [32K,64K) ---
    __syncthreads();           // all mainloop smem reads done before reuse
    int* loS = reinterpret_cast<int*>(smem);
    int* hdS = reinterpret_cast<int*>(smem + 32768);
#pragma unroll
    for (int i = 0; i < 8; ++i)
#pragma unroll
        for (int j = 0; j < 4; ++j) {
            loS[(wid + 8 * i) * BN + lane + 32 * j] = accLo[i][j];
            hdS[(wid + 8 * i) * BN + lane + 32 * j] = accHd[i][j];
        }
    __syncthreads();

    // --- epilogue: combine, scale, bias, store fp32 ---
#pragma unroll
    for (int mt = 0; mt < 2; ++mt) {
        const int rl = wm * 32 + mt * 16 + (lane >> 2);
        const int r0 = m0 + rl;
        const float s0 = g_scale[r0];
        const float s1 = g_scale[r0 + 8];
#pragma unroll
        for (int nt = 0; nt < 4; ++nt) {
            const int cl = wn * 32 + nt * 8 + 2 * (lane & 3);
            const int col = n0 + cl;
            const float bv0 = __ldg(bias + col);
            const float bv1 = __ldg(bias + col + 1);
            const int* h = accH[mt][nt];
            const int i00 = rl * BN + cl, i01 = i00 + 1;
            const int i10 = (rl + 8) * BN + cl, i11 = i10 + 1;
            float2 o0, o1;
            o0.x = s0 * (float)(256 * (h[0] + hdS[i00]) + loS[i00]) + bv0;
            o0.y = s0 * (float)(256 * (h[1] + hdS[i01]) + loS[i01]) + bv1;
            o1.x = s1 * (float)(256 * (h[2] + hdS[i10]) + loS[i10]) + bv0;
            o1.y = s1 * (float)(256 * (h[3] + hdS[i11]) + loS[i11]) + bv1;
            *reinterpret_cast<float2*>(out + (size_t)r0 * N_DIM + col) = o0;
            *reinterpret_cast<float2*>(out + (size_t)(r0 + 8) * N_DIM + col) = o1;
        }
    }
#undef PREFETCH
}

// ---------------------------------------------------------------------------
// Launch
// ---------------------------------------------------------------------------
extern "C" void kernel_launch(void* const* d_in, const int* in_sizes, int n_in,
                              void* d_out, int out_size) {
    const float* x    = (const float*)d_in[0];
    const float* w    = (const float*)d_in[1];
    const float* bias = (const float*)d_in[2];
    float* out = (float*)d_out;

    quant_all_kernel<<<M_DIM + (N_DIM * K_DIM / 4) / 256, 256>>>(x, w);

    cudaFuncSetAttribute(gemm_s8_kernel,
                         cudaFuncAttributeMaxDynamicSharedMemorySize, SMEM_TOTAL);
    dim3 grid(N_DIM / BN, M_DIM / BM);   // (32, 128): n fastest -> W L2-resident
    gemm_s8_kernel<<<grid, 256, SMEM_TOTAL>>>(bias, out);
}